// round 9
// baseline (speedup 1.0000x reference)
#include <cuda_runtime.h>
#include <math.h>

#define Bz 8
#define Tz 512
#define Ez 64
#define Hz 128
#define TC 32
#define NC 16
#define NCTA (Bz*NC)
#define THREADS 1024

// Pitches (floats)
#define P1 68
#define PK 68
#define PDY 68
#define P2 132
#define PH 132

// Per-CTA partial layout (floats): D-weighted grads only
#define OF2_W1D 0
#define OF2_B1D 8192
#define OF2_W2D 8320
#define OF2_B2D 16512
#define PARTSZ2 16576

// Output offsets
#define O_LOSS 0
#define O_MW1  512
#define O_MB1  66048
#define O_MW2  67072
#define O_MB2  132608
#define O_SW1  133120
#define O_SB1  198656
#define O_SW2  199680
#define O_SB2  265216

#define LNETA  (-0.0512932943875506f)
#define LNBE   (-6.8564619845945864f)
#define INV949 (1.0537407798735f)

__device__ __align__(16) float g_np[2*NCTA*Ez];
__device__ __align__(16) float g_lossp[Bz*Tz];
__device__ __align__(16) float g_part[NCTA*PARTSZ2];
__device__ __align__(16) float g_corr[Bz*PARTSZ2];
__device__ unsigned g_count;
__device__ volatile unsigned g_phase;

__device__ __forceinline__ void grid_barrier(int tid) {
    __threadfence();
    __syncthreads();
    if (tid == 0) {
        unsigned my = g_phase;
        unsigned old = atomicAdd(&g_count, 1);
        if (old == NCTA - 1) {
            g_count = 0;
            __threadfence();
            atomicAdd((unsigned*)&g_phase, 1);
        } else {
            while (g_phase == my) { }
        }
        __threadfence();
    }
    __syncthreads();
}

// ---------------------------------------------------------------------------
// Single fused kernel. 128 CTAs x 1024 threads (32 warps/SM), ~146KB smem.
// ---------------------------------------------------------------------------
#define SM_FLOATS 36576
__global__ __launch_bounds__(THREADS, 1) void k_main(
        const float* __restrict__ x,
        const float* __restrict__ WK, const float* __restrict__ WV,
        const float* __restrict__ W1, const float* __restrict__ b1,
        const float* __restrict__ W2, const float* __restrict__ b2,
        const float* __restrict__ SW1, const float* __restrict__ Sb1,
        const float* __restrict__ SW2, const float* __restrict__ Sb2,
        float* __restrict__ out) {
    extern __shared__ float sm[];
    // Region A (8704): phase0 = WK|WV ; later = W1
    float* sWK  = sm;                 // 64 x P1
    float* sWV  = sm + 4352;
    float* sW1  = sm;                 // 128 x P1 overlay
    // Region B (8448): phase0 = x ; later = W2
    float* sx   = sm + 8704;          // 32 x PK (phase0 only)
    float* sW2  = sm + 8704;          // 64 x P2 overlay
    float* sk   = sm + 17152;         // 32 x PK
    float* sv   = sk  + 2176;         // 32 x PK
    float* sh   = sv  + 2176;         // 32 x PH
    float* ss   = sh  + 4224;         // 32 x PH
    float* sdy  = ss  + 4224;         // 32 x PDY
    float* sdz  = sdy + 2176;         // 32 x PH
    float* scD  = sdz + 4224;         // 32
    float* scR  = scD + 32;           // 32
    float* sinvk= scR + 32;           // 64
    float* sinvv= sinvk + 64;         // 64
    float* sloss= sinvv + 64;         // 32  -> 36576 total

    const int bid = blockIdx.x;
    const int b   = bid >> 4;
    const int t0  = (bid & 15) * TC;
    const int tid = threadIdx.x;
    const int lane = tid & 31, wp = tid >> 5;   // 32 warps

    // ---- phase 0 loads ----
    {   // WK/WV: 1024 float4s exactly, one per thread
        int i = tid*4;
        int e = i >> 6, j = i & 63;
        *(float4*)&sWK[e*P1 + j] = *(const float4*)&WK[i];
        *(float4*)&sWV[e*P1 + j] = *(const float4*)&WV[i];
    }
    if (tid < 512) {
        int i = tid*4;
        *(float4*)&sx[(i >> 6)*PK + (i & 63)] = *(const float4*)&x[(b*Tz + t0)*64 + i];
    }
    if (tid >= 512 && tid < 544) {
        int tl = tid - 512;
        float n1 = (float)(Tz - (t0 + tl));
        scD[tl] = -0.05f * __expf(n1 * LNETA);
        scR[tl] = -INV949 * __expf(n1 * LNBE);
    }
    if (tid >= 544 && tid < 576) sloss[tid - 544] = 0.f;
    __syncthreads();

    // ---- phase 0: silu projections. lane=token; warp owns 4 e-rows ----
    {
        const int rb = (wp & 15) * 4;
        const bool isK = (wp < 16);
        const float* sW = isK ? sWK : sWV;
        float acc[4] = {0.f, 0.f, 0.f, 0.f};
        for (int j = 0; j < 64; j += 4) {
            float4 xq = *(const float4*)&sx[lane*PK + j];
            #pragma unroll
            for (int r = 0; r < 4; r++) {
                float4 w = *(const float4*)&sW[(rb + r)*P1 + j];
                acc[r] += w.x*xq.x + w.y*xq.y + w.z*xq.z + w.w*xq.w;
            }
        }
        float val[4];
        #pragma unroll
        for (int r = 0; r < 4; r++) {
            float z = acc[r];
            val[r] = z / (1.f + __expf(-z));
        }
        float* dst = isK ? sk : sv;
        *(float4*)&dst[lane*PK + rb] = make_float4(val[0], val[1], val[2], val[3]);
        float* nrm = isK ? sinvk : sinvv;
        #pragma unroll
        for (int r = 0; r < 4; r++) {
            float q = val[r] * val[r];
            #pragma unroll
            for (int o = 16; o; o >>= 1) q += __shfl_xor_sync(0xffffffffu, q, o);
            if (lane == 0) nrm[rb + r] = q;
        }
    }
    __syncthreads();

    if (tid < 64)       g_np[bid*64 + tid] = sinvk[tid];
    else if (tid < 128) g_np[(NCTA + bid)*64 + tid - 64] = sinvv[tid - 64];

    // ---- grid barrier #1 (W1/W2 loads overlap the spin) ----
    __threadfence();
    __syncthreads();
    if (tid == 0) {
        unsigned my = g_phase;
        unsigned old = atomicAdd(&g_count, 1);
        if (old == NCTA - 1) {
            g_count = 0;
            __threadfence();
            atomicAdd((unsigned*)&g_phase, 1);
        } else {
            while (g_phase == my) { }
        }
        __threadfence();
    }
    #pragma unroll
    for (int i = tid*4; i < 8192; i += 4096)
        *(float4*)&sW1[(i >> 6)*P1 + (i & 63)] = *(const float4*)&W1[b*8192 + i];
    #pragma unroll
    for (int i = tid*4; i < 8192; i += 4096)
        *(float4*)&sW2[(i >> 7)*P2 + (i & 127)] = *(const float4*)&W2[b*8192 + i];
    __syncthreads();

    // ---- reduce norms ----
    if (tid < 64) {
        float s = 0.f, s2 = 0.f;
        #pragma unroll
        for (int c = 0; c < NC; c++) {
            s  += g_np[(b*NC + c)*64 + tid];
            s2 += g_np[(NCTA + b*NC + c)*64 + tid];
        }
        sinvk[tid] = (s  > 0.f) ? rsqrtf(s)  : 0.f;
        sinvv[tid] = (s2 > 0.f) ? rsqrtf(s2) : 0.f;
    }
    __syncthreads();

    // ---- normalize k, v ----
    if (tid < 512) {
        int t = tid >> 4, e4 = (tid & 15) * 4;
        float4 q = *(const float4*)&sk[t*PK + e4];
        q.x *= sinvk[e4]; q.y *= sinvk[e4+1]; q.z *= sinvk[e4+2]; q.w *= sinvk[e4+3];
        *(float4*)&sk[t*PK + e4] = q;
        float4 p = *(const float4*)&sv[t*PK + e4];
        p.x *= sinvv[e4]; p.y *= sinvv[e4+1]; p.z *= sinvv[e4+2]; p.w *= sinvv[e4+3];
        *(float4*)&sv[t*PK + e4] = p;
    }
    __syncthreads();

    // ---- z = W1 k + b1 ; h = silu(z). lane=token; warp owns 4 h-rows ----
    {
        const int hb = wp * 4;
        float acc[4];
        #pragma unroll
        for (int r = 0; r < 4; r++) acc[r] = b1[b*128 + hb + r];
        for (int j = 0; j < 64; j += 4) {
            float4 kq = *(const float4*)&sk[lane*PK + j];
            #pragma unroll
            for (int r = 0; r < 4; r++) {
                float4 w = *(const float4*)&sW1[(hb + r)*P1 + j];
                acc[r] += w.x*kq.x + w.y*kq.y + w.z*kq.z + w.w*kq.w;
            }
        }
        float hv[4], sgv[4];
        #pragma unroll
        for (int r = 0; r < 4; r++) {
            float z = acc[r];
            float sg = 1.f / (1.f + __expf(-z));
            sgv[r] = sg;
            hv[r]  = z * sg;
        }
        *(float4*)&sh[lane*PH + hb] = make_float4(hv[0], hv[1], hv[2], hv[3]);
        *(float4*)&ss[lane*PH + hb] = make_float4(sgv[0], sgv[1], sgv[2], sgv[3]);
    }
    __syncthreads();

    // ---- y = W2 h + b2 ; dy = (y-v)/256 * cD (prefold) ; loss ----
    {
        const int rb2 = wp * 2;
        float acc0 = b2[b*64 + rb2];
        float acc1 = b2[b*64 + rb2 + 1];
        for (int j = 0; j < 128; j += 4) {
            float4 hq = *(const float4*)&sh[lane*PH + j];
            float4 w0 = *(const float4*)&sW2[(rb2    )*P2 + j];
            float4 w1 = *(const float4*)&sW2[(rb2 + 1)*P2 + j];
            acc0 += w0.x*hq.x + w0.y*hq.y + w0.z*hq.z + w0.w*hq.w;
            acc1 += w1.x*hq.x + w1.y*hq.y + w1.z*hq.z + w1.w*hq.w;
        }
        float2 vv = *(const float2*)&sv[lane*PK + rb2];
        float d0 = acc0 - vv.x, d1 = acc1 - vv.y;
        float fold = (1.f/256.f) * scD[lane];
        *(float2*)&sdy[lane*PDY + rb2] = make_float2(d0*fold, d1*fold);
        atomicAdd(&sloss[lane], d0*d0 + d1*d1);
    }
    __syncthreads();

    // ---- dh = W2^T dy ; dz = dh*dsilu. lane=token; warp owns 4 h-rows ----
    {
        const int hb = wp * 4;
        float acc[4] = {0.f, 0.f, 0.f, 0.f};
        for (int e = 0; e < 64; e += 4) {
            float4 dq = *(const float4*)&sdy[lane*PDY + e];
            const float dqa[4] = {dq.x, dq.y, dq.z, dq.w};
            #pragma unroll
            for (int ee = 0; ee < 4; ee++) {
                float4 w = *(const float4*)&sW2[(e + ee)*P2 + hb];
                acc[0] += w.x * dqa[ee];
                acc[1] += w.y * dqa[ee];
                acc[2] += w.z * dqa[ee];
                acc[3] += w.w * dqa[ee];
            }
        }
        float4 sg4 = *(const float4*)&ss[lane*PH + hb];
        float4 hv4 = *(const float4*)&sh[lane*PH + hb];
        float dz0 = acc[0] * (sg4.x + hv4.x*(1.f - sg4.x));
        float dz1 = acc[1] * (sg4.y + hv4.y*(1.f - sg4.y));
        float dz2 = acc[2] * (sg4.z + hv4.z*(1.f - sg4.z));
        float dz3 = acc[3] * (sg4.w + hv4.w*(1.f - sg4.w));
        *(float4*)&sdz[lane*PH + hb] = make_float4(dz0, dz1, dz2, dz3);
    }
    __syncthreads();

    // ---- D-weighted outer products: 2h x 4e tile per thread ----
    const int e0 = (tid & 15) * 4;
    const int h0 = (tid >> 4) * 2;
    float a1[2][4], a2[4][2];
    #pragma unroll
    for (int i = 0; i < 2; i++)
        #pragma unroll
        for (int j = 0; j < 4; j++) { a1[i][j] = 0.f; a2[j][i] = 0.f; }

    for (int t = 0; t < TC; t++) {
        float4 kq = *(const float4*)&sk[t*PK + e0];
        float2 zq = *(const float2*)&sdz[t*PH + h0];
        a1[0][0] += zq.x*kq.x; a1[0][1] += zq.x*kq.y;
        a1[0][2] += zq.x*kq.z; a1[0][3] += zq.x*kq.w;
        a1[1][0] += zq.y*kq.x; a1[1][1] += zq.y*kq.y;
        a1[1][2] += zq.y*kq.z; a1[1][3] += zq.y*kq.w;
        float4 dq = *(const float4*)&sdy[t*PDY + e0];
        float2 hq = *(const float2*)&sh[t*PH + h0];
        a2[0][0] += dq.x*hq.x; a2[0][1] += dq.x*hq.y;
        a2[1][0] += dq.y*hq.x; a2[1][1] += dq.y*hq.y;
        a2[2][0] += dq.z*hq.x; a2[2][1] += dq.z*hq.y;
        a2[3][0] += dq.w*hq.x; a2[3][1] += dq.w*hq.y;
    }

    float* p = g_part + (size_t)bid * PARTSZ2;
    #pragma unroll
    for (int i = 0; i < 2; i++)
        *(float4*)&p[OF2_W1D + (h0 + i)*64 + e0] =
            make_float4(a1[i][0], a1[i][1], a1[i][2], a1[i][3]);
    #pragma unroll
    for (int j = 0; j < 4; j++)
        *(float2*)&p[OF2_W2D + (e0 + j)*128 + h0] = make_float2(a2[j][0], a2[j][1]);
    if (tid < 128) {
        float aD = 0.f;
        for (int t = 0; t < TC; t++) aD += sdz[t*PH + tid];
        p[OF2_B1D + tid] = aD;
    } else if (tid < 192) {
        int e = tid - 128;
        float aD = 0.f;
        for (int t = 0; t < TC; t++) aD += sdy[t*PDY + e];
        p[OF2_B2D + e] = aD;
    }
    if (tid < TC) g_lossp[b*Tz + t0 + tid] = sloss[tid];

    // ---- correction (last chunk per batch; ratio scR = cc/cd) ----
    if ((bid & 15) == 15) {
        #pragma unroll
        for (int i = 0; i < 2; i++)
            #pragma unroll
            for (int j = 0; j < 4; j++) { a1[i][j] = 0.f; a2[j][i] = 0.f; }
        for (int t = 16; t < TC; t++) {
            float rr = scR[t];
            float4 kq = *(const float4*)&sk[t*PK + e0];
            float2 zq = *(const float2*)&sdz[t*PH + h0];
            float z0 = rr*zq.x, z1 = rr*zq.y;
            a1[0][0] += z0*kq.x; a1[0][1] += z0*kq.y;
            a1[0][2] += z0*kq.z; a1[0][3] += z0*kq.w;
            a1[1][0] += z1*kq.x; a1[1][1] += z1*kq.y;
            a1[1][2] += z1*kq.z; a1[1][3] += z1*kq.w;
            float4 dq = *(const float4*)&sdy[t*PDY + e0];
            float2 hq = *(const float2*)&sh[t*PH + h0];
            float q0 = rr*dq.x, q1 = rr*dq.y, q2 = rr*dq.z, q3 = rr*dq.w;
            a2[0][0] += q0*hq.x; a2[0][1] += q0*hq.y;
            a2[1][0] += q1*hq.x; a2[1][1] += q1*hq.y;
            a2[2][0] += q2*hq.x; a2[2][1] += q2*hq.y;
            a2[3][0] += q3*hq.x; a2[3][1] += q3*hq.y;
        }
        float* q = g_corr + (size_t)b * PARTSZ2;
        #pragma unroll
        for (int i = 0; i < 2; i++)
            *(float4*)&q[OF2_W1D + (h0 + i)*64 + e0] =
                make_float4(a1[i][0], a1[i][1], a1[i][2], a1[i][3]);
        #pragma unroll
        for (int j = 0; j < 4; j++)
            *(float2*)&q[OF2_W2D + (e0 + j)*128 + h0] = make_float2(a2[j][0], a2[j][1]);
        if (tid < 128) {
            float aC = 0.f;
            for (int t = 16; t < TC; t++) aC += scR[t] * sdz[t*PH + tid];
            q[OF2_B1D + tid] = aC;
        } else if (tid < 192) {
            int e = tid - 128;
            float aC = 0.f;
            for (int t = 16; t < TC; t++) aC += scR[t] * sdy[t*PDY + e];
            q[OF2_B2D + e] = aC;
        }
    }

    // ---- grid barrier #2, then fused output reduction ----
    grid_barrier(tid);

    const float qT = __expf(-26.262166726f);    // 0.95^512
    const float aT = qT * 1.0010537407f;
    int gt = bid * THREADS + tid;
    if (gt < 512) {
        float s = 0.f;
        #pragma unroll
        for (int bb = 0; bb < Bz; bb++) s += g_lossp[bb*Tz + gt];
        out[O_LOSS + gt] = s * (1.f/512.f);
        return;
    }
    int j = gt - 512;
    int ofD, nvec_b, segM, segS;
    const float* S0p;
    if (j < 16384) {
        ofD = OF2_W1D; nvec_b = 2048; segM = O_MW1; segS = O_SW1; S0p = SW1;
    } else if ((j -= 16384) < 256) {
        ofD = OF2_B1D; nvec_b = 32;   segM = O_MB1; segS = O_SB1; S0p = Sb1;
    } else if ((j -= 256) < 16384) {
        ofD = OF2_W2D; nvec_b = 2048; segM = O_MW2; segS = O_SW2; S0p = SW2;
    } else if ((j -= 16384) < 128) {
        ofD = OF2_B2D; nvec_b = 16;   segM = O_MB2; segS = O_SB2; S0p = Sb2;
    } else return;

    int bb = j / nvec_b;
    int r = (j - bb*nvec_b) * 4;
    const float* pp = g_part + (size_t)(bb*NC) * PARTSZ2 + ofD + r;
    float4 rD = make_float4(0.f, 0.f, 0.f, 0.f);
    #pragma unroll
    for (int c = 0; c < NC; c++) {
        float4 v = *(const float4*)(pp + (size_t)c * PARTSZ2);
        rD.x += v.x; rD.y += v.y; rD.z += v.z; rD.w += v.w;
    }
    float4 cr = *(const float4*)(g_corr + (size_t)bb * PARTSZ2 + ofD + r);
    int gidx = bb * (nvec_b*4) + r;
    float4 s0 = *(const float4*)(S0p + gidx);
    float4 M, S;
    M.x = aT*s0.x + rD.x*INV949 + cr.x;  S.x = qT*s0.x + rD.x;
    M.y = aT*s0.y + rD.y*INV949 + cr.y;  S.y = qT*s0.y + rD.y;
    M.z = aT*s0.z + rD.z*INV949 + cr.z;  S.z = qT*s0.z + rD.z;
    M.w = aT*s0.w + rD.w*INV949 + cr.w;  S.w = qT*s0.w + rD.w;
    *(float4*)(out + segM + gidx) = M;
    *(float4*)(out + segS + gidx) = S;
}

extern "C" void kernel_launch(void* const* d_in, const int* in_sizes, int n_in,
                              void* d_out, int out_size) {
    const float* x   = (const float*)d_in[0];
    const float* WK  = (const float*)d_in[1];
    const float* WV  = (const float*)d_in[2];
    const float* W1  = (const float*)d_in[3];
    const float* b1  = (const float*)d_in[4];
    const float* W2  = (const float*)d_in[5];
    const float* b2  = (const float*)d_in[6];
    const float* SW1 = (const float*)d_in[7];
    const float* Sb1 = (const float*)d_in[8];
    const float* SW2 = (const float*)d_in[9];
    const float* Sb2 = (const float*)d_in[10];
    float* out = (float*)d_out;

    static const size_t smem_main = SM_FLOATS * sizeof(float);
    cudaFuncSetAttribute(k_main, cudaFuncAttributeMaxDynamicSharedMemorySize,
                         (int)smem_main);

    k_main<<<NCTA, THREADS, smem_main>>>(x, WK, WV, W1, b1, W2, b2,
                                         SW1, Sb1, SW2, Sb2, out);
}

// round 10
// speedup vs baseline: 1.1901x; 1.1901x over previous
#include <cuda_runtime.h>
#include <math.h>

typedef unsigned long long u64;

// Packed fp32x2 helpers (Blackwell dual-fp32 pipe)
__device__ __forceinline__ u64 splat2(float v) {
    u64 r; asm("mov.b64 %0, {%1, %1};" : "=l"(r) : "f"(v)); return r;
}
__device__ __forceinline__ u64 pk2(float a, float b) {
    u64 r; asm("mov.b64 %0, {%1, %2};" : "=l"(r) : "f"(a), "f"(b)); return r;
}
__device__ __forceinline__ u64 fma2(u64 a, u64 b, u64 c) {
    u64 d; asm("fma.rn.f32x2 %0, %1, %2, %3;" : "=l"(d) : "l"(a), "l"(b), "l"(c));
    return d;
}
__device__ __forceinline__ u64 mul2(u64 a, u64 b) {
    u64 d; asm("mul.rn.f32x2 %0, %1, %2;" : "=l"(d) : "l"(a), "l"(b)); return d;
}
__device__ __forceinline__ float2 up2(u64 a) {
    float2 f; asm("mov.b64 {%0, %1}, %2;" : "=f"(f.x), "=f"(f.y) : "l"(a)); return f;
}
__device__ __forceinline__ float hsum2(u64 a) { float2 f = up2(a); return f.x + f.y; }

#define Bz 8
#define Tz 512
#define Ez 64
#define Hz 128
#define TC 32
#define NC 16
#define NCTA (Bz*NC)

#define P1 68
#define P2 132

#define OF2_W1D 0
#define OF2_B1D 8192
#define OF2_W2D 8320
#define OF2_B2D 16512
#define PARTSZ2 16576

#define O_LOSS 0
#define O_MW1  512
#define O_MB1  66048
#define O_MW2  67072
#define O_MB2  132608
#define O_SW1  133120
#define O_SB1  198656
#define O_SW2  199680
#define O_SB2  265216

#define LNETA  (-0.0512932943875506f)
#define LNBETA (-6.9077552789821370f)
#define INV949 (1.0537407798735f)
#define CORRK  (0.0526870389936f)

__device__ __align__(16) float g_np[2*NCTA*Ez];
__device__ __align__(16) float g_lossp[Bz*Tz];
__device__ __align__(16) float g_part[NCTA*PARTSZ2];
__device__ __align__(16) float g_corr[Bz*PARTSZ2];
__device__ unsigned g_count;
__device__ volatile unsigned g_phase;

__device__ __forceinline__ void grid_barrier(int tid) {
    __threadfence();
    __syncthreads();
    if (tid == 0) {
        unsigned my = g_phase;
        unsigned old = atomicAdd(&g_count, 1);
        if (old == NCTA - 1) {
            g_count = 0;
            __threadfence();
            atomicAdd((unsigned*)&g_phase, 1);
        } else {
            while (g_phase == my) { }
        }
        __threadfence();
    }
    __syncthreads();
}

// ---------------------------------------------------------------------------
// Single fused kernel (R7 structure + packed f32x2 math in all hot loops).
// 128 CTAs x 512 threads, 143KB smem -> 1 CTA/SM, all co-resident.
// ---------------------------------------------------------------------------
#define SM_FLOATS 35840
__global__ __launch_bounds__(512, 1) void k_main(const float* __restrict__ x,
                                                 const float* __restrict__ WK,
                                                 const float* __restrict__ WV,
                                                 const float* __restrict__ W1,
                                                 const float* __restrict__ b1,
                                                 const float* __restrict__ W2,
                                                 const float* __restrict__ b2,
                                                 const float* __restrict__ SW1,
                                                 const float* __restrict__ Sb1,
                                                 const float* __restrict__ SW2,
                                                 const float* __restrict__ Sb2,
                                                 float* __restrict__ out) {
    extern __shared__ float sm[];
    float* sWK  = sm;                 // 64 x P1
    float* sWV  = sm + 4352;          // 64 x P1
    float* sW1  = sm;                 // 128 x P1 overlay
    float* sx   = sm + 8704;          // 32x64 (phase0 only)
    float* sW2  = sm + 8704;          // 64 x P2 overlay
    float* sk   = sm + 17152;         // 32x64
    float* sv   = sk  + 2048;         // 32x64
    float* sh   = sv  + 2048;         // 32x128
    float* ss   = sh  + 4096;         // 32x128
    float* sdy  = ss  + 4096;         // 32x64
    float* sdz  = sdy + 2048;         // 32x128
    float* scD  = sdz + 4096;         // 32
    float* scC  = scD + 32;           // 32
    float* sinvk= scC + 32;           // 64
    float* sinvv= sinvk + 64;         // 64
    float* sloss= sinvv + 64;         // 32  -> 35808 <= 35840

    const int bid = blockIdx.x;
    const int b   = bid >> 4;
    const int t0  = (bid & 15) * TC;
    const int tid = threadIdx.x;
    const int lane = tid & 31, wp = tid >> 5;   // 16 warps, 2 tokens each

    // ---- phase 0 loads ----
    #pragma unroll
    for (int i = tid*4; i < 4096; i += 2048) {
        int e = i >> 6, j = i & 63;
        *(float4*)&sWK[e*P1 + j] = *(const float4*)&WK[i];
        *(float4*)&sWV[e*P1 + j] = *(const float4*)&WV[i];
    }
    *(float4*)&sx[tid*4] = *(const float4*)&x[(b*Tz + t0)*64 + tid*4];
    if (tid < 64)       sinvk[tid] = 0.f;
    else if (tid < 128) sinvv[tid - 64] = 0.f;
    if (tid >= 128 && tid < 160) {
        int tl = tid - 128;
        float n1 = (float)(Tz - (t0 + tl));
        scD[tl] = -0.05f * __expf(n1 * LNETA);
        scC[tl] = CORRK  * __expf(n1 * LNBETA);
    }
    __syncthreads();

    // ---- phase 0: silu projections (packed f32x2) ----
    {
        u64 accp[4][2];
        #pragma unroll
        for (int r = 0; r < 4; r++) { accp[r][0] = 0ULL; accp[r][1] = 0ULL; }
        for (int j = 0; j < 64; j += 4) {
            ulonglong2 xq[2];
            #pragma unroll
            for (int tt = 0; tt < 2; tt++)
                xq[tt] = *(const ulonglong2*)&sx[(wp*2 + tt)*64 + j];
            ulonglong2 wq[4];
            wq[0] = *(const ulonglong2*)&sWK[(lane     )*P1 + j];
            wq[1] = *(const ulonglong2*)&sWK[(lane + 32)*P1 + j];
            wq[2] = *(const ulonglong2*)&sWV[(lane     )*P1 + j];
            wq[3] = *(const ulonglong2*)&sWV[(lane + 32)*P1 + j];
            #pragma unroll
            for (int r = 0; r < 4; r++)
                #pragma unroll
                for (int tt = 0; tt < 2; tt++) {
                    accp[r][tt] = fma2(wq[r].x, xq[tt].x, accp[r][tt]);
                    accp[r][tt] = fma2(wq[r].y, xq[tt].y, accp[r][tt]);
                }
        }
        #pragma unroll
        for (int r = 0; r < 4; r++) {
            int e = lane + 32*(r & 1);
            float sq = 0.f;
            #pragma unroll
            for (int tt = 0; tt < 2; tt++) {
                float z = hsum2(accp[r][tt]);
                float s = z / (1.f + __expf(-z));
                int t = wp*2 + tt;
                if (r < 2) sk[t*64 + e] = s;
                else       sv[t*64 + e] = s;
                sq += s * s;
            }
            if (r < 2) atomicAdd(&sinvk[e], sq);
            else       atomicAdd(&sinvv[e], sq);
        }
    }
    __syncthreads();

    if (tid < 64)       g_np[bid*64 + tid] = sinvk[tid];
    else if (tid < 128) g_np[(NCTA + bid)*64 + tid - 64] = sinvv[tid - 64];

    // ---- grid barrier #1 (W1/W2 loads overlap the spin) ----
    __threadfence();
    __syncthreads();
    if (tid == 0) {
        unsigned my = g_phase;
        unsigned old = atomicAdd(&g_count, 1);
        if (old == NCTA - 1) {
            g_count = 0;
            __threadfence();
            atomicAdd((unsigned*)&g_phase, 1);
        } else {
            while (g_phase == my) { }
        }
        __threadfence();
    }
    #pragma unroll
    for (int i = tid*4; i < 8192; i += 2048)
        *(float4*)&sW1[(i >> 6)*P1 + (i & 63)] = *(const float4*)&W1[b*8192 + i];
    #pragma unroll
    for (int i = tid*4; i < 8192; i += 2048)
        *(float4*)&sW2[(i >> 7)*P2 + (i & 127)] = *(const float4*)&W2[b*8192 + i];
    __syncthreads();

    // ---- reduce norms ----
    if (tid < 64) {
        float s = 0.f, s2 = 0.f;
        #pragma unroll
        for (int c = 0; c < NC; c++) {
            s  += g_np[(b*NC + c)*64 + tid];
            s2 += g_np[(NCTA + b*NC + c)*64 + tid];
        }
        sinvk[tid] = (s  > 0.f) ? rsqrtf(s)  : 0.f;
        sinvv[tid] = (s2 > 0.f) ? rsqrtf(s2) : 0.f;
    }
    __syncthreads();

    // ---- normalize k, v ----
    {
        int t = tid >> 4, e4 = (tid & 15) * 4;
        float4 q = *(const float4*)&sk[t*64 + e4];
        q.x *= sinvk[e4]; q.y *= sinvk[e4+1]; q.z *= sinvk[e4+2]; q.w *= sinvk[e4+3];
        *(float4*)&sk[t*64 + e4] = q;
        float4 p = *(const float4*)&sv[t*64 + e4];
        p.x *= sinvv[e4]; p.y *= sinvv[e4+1]; p.z *= sinvv[e4+2]; p.w *= sinvv[e4+3];
        *(float4*)&sv[t*64 + e4] = p;
    }
    __syncthreads();

    // ---- z = W1 k + b1 ; h = silu(z) (packed) ----
    {
        u64 accp[4][2];
        #pragma unroll
        for (int r = 0; r < 4; r++) { accp[r][0] = 0ULL; accp[r][1] = 0ULL; }
        for (int j = 0; j < 64; j += 4) {
            ulonglong2 kq[2];
            #pragma unroll
            for (int tt = 0; tt < 2; tt++)
                kq[tt] = *(const ulonglong2*)&sk[(wp*2 + tt)*64 + j];
            ulonglong2 wq[4];
            #pragma unroll
            for (int r = 0; r < 4; r++)
                wq[r] = *(const ulonglong2*)&sW1[(lane + 32*r)*P1 + j];
            #pragma unroll
            for (int r = 0; r < 4; r++)
                #pragma unroll
                for (int tt = 0; tt < 2; tt++) {
                    accp[r][tt] = fma2(wq[r].x, kq[tt].x, accp[r][tt]);
                    accp[r][tt] = fma2(wq[r].y, kq[tt].y, accp[r][tt]);
                }
        }
        #pragma unroll
        for (int r = 0; r < 4; r++) {
            float bv = b1[b*128 + lane + 32*r];
            #pragma unroll
            for (int tt = 0; tt < 2; tt++) {
                int idx = (wp*2 + tt)*128 + lane + 32*r;
                float z  = bv + hsum2(accp[r][tt]);
                float sg = 1.f / (1.f + __expf(-z));
                ss[idx] = sg;
                sh[idx] = z * sg;
            }
        }
    }
    __syncthreads();

    // ---- y = W2 h + b2 ; dy = (y - v)/256 ; loss (packed) ----
    {
        u64 accp[2][2];
        #pragma unroll
        for (int r = 0; r < 2; r++) { accp[r][0] = 0ULL; accp[r][1] = 0ULL; }
        for (int j = 0; j < 128; j += 4) {
            ulonglong2 hq[2];
            #pragma unroll
            for (int tt = 0; tt < 2; tt++)
                hq[tt] = *(const ulonglong2*)&sh[(wp*2 + tt)*128 + j];
            ulonglong2 w0 = *(const ulonglong2*)&sW2[(lane     )*P2 + j];
            ulonglong2 w1 = *(const ulonglong2*)&sW2[(lane + 32)*P2 + j];
            #pragma unroll
            for (int tt = 0; tt < 2; tt++) {
                accp[0][tt] = fma2(w0.x, hq[tt].x, accp[0][tt]);
                accp[0][tt] = fma2(w0.y, hq[tt].y, accp[0][tt]);
                accp[1][tt] = fma2(w1.x, hq[tt].x, accp[1][tt]);
                accp[1][tt] = fma2(w1.y, hq[tt].y, accp[1][tt]);
            }
        }
        float bv0 = b2[b*64 + lane];
        float bv1 = b2[b*64 + lane + 32];
        #pragma unroll
        for (int tt = 0; tt < 2; tt++) {
            int t = wp*2 + tt;
            float d0 = bv0 + hsum2(accp[0][tt]) - sv[t*64 + lane];
            float d1 = bv1 + hsum2(accp[1][tt]) - sv[t*64 + lane + 32];
            sdy[t*64 + lane]      = d0 * (1.f/256.f);
            sdy[t*64 + lane + 32] = d1 * (1.f/256.f);
            float l = d0*d0 + d1*d1;
            #pragma unroll
            for (int o = 16; o; o >>= 1) l += __shfl_xor_sync(0xffffffffu, l, o);
            if (lane == 0) sloss[t] = l;
        }
    }
    __syncwarp();

    // ---- dh = W2^T dy ; dz = dh * dsilu (packed over e-pairs) ----
    {
        u64 accp[4][2];
        #pragma unroll
        for (int r = 0; r < 4; r++) { accp[r][0] = 0ULL; accp[r][1] = 0ULL; }
        for (int e = 0; e < 64; e += 4) {
            ulonglong2 dv[2];
            #pragma unroll
            for (int tt = 0; tt < 2; tt++)
                dv[tt] = *(const ulonglong2*)&sdy[(wp*2 + tt)*64 + e];
            #pragma unroll
            for (int ee = 0; ee < 2; ee++) {   // pairs (e+2ee, e+2ee+1)
                #pragma unroll
                for (int r = 0; r < 4; r++) {
                    u64 wpk = pk2(sW2[(e + 2*ee    )*P2 + lane + 32*r],
                                  sW2[(e + 2*ee + 1)*P2 + lane + 32*r]);
                    accp[r][0] = fma2(wpk, ee ? dv[0].y : dv[0].x, accp[r][0]);
                    accp[r][1] = fma2(wpk, ee ? dv[1].y : dv[1].x, accp[r][1]);
                }
            }
        }
        #pragma unroll
        for (int r = 0; r < 4; r++)
            #pragma unroll
            for (int tt = 0; tt < 2; tt++) {
                int idx = (wp*2 + tt)*128 + lane + 32*r;
                float sg = ss[idx], hv = sh[idx];
                sdz[idx] = hsum2(accp[r][tt]) * (sg + hv * (1.f - sg));
            }
    }
    __syncthreads();

    // ---- D-weighted outer products (packed; cd folded at use) ----
    const int e0 = (tid & 15) * 4;
    const int h0 = (tid >> 4) * 4;
    u64 a1p[4][2], a2p[4][2];
    #pragma unroll
    for (int i = 0; i < 4; i++) {
        a1p[i][0] = 0ULL; a1p[i][1] = 0ULL;
        a2p[i][0] = 0ULL; a2p[i][1] = 0ULL;
    }

    for (int t = 0; t < TC; t++) {
        u64 cdp = splat2(scD[t]);
        ulonglong2 kq = *(const ulonglong2*)&sk[t*64 + e0];
        u64 ks0 = mul2(kq.x, cdp), ks1 = mul2(kq.y, cdp);
        float4 zq = *(const float4*)&sdz[t*128 + h0];
        u64 dz0 = splat2(zq.x), dz1 = splat2(zq.y);
        u64 dz2 = splat2(zq.z), dz3 = splat2(zq.w);
        a1p[0][0] = fma2(dz0, ks0, a1p[0][0]); a1p[0][1] = fma2(dz0, ks1, a1p[0][1]);
        a1p[1][0] = fma2(dz1, ks0, a1p[1][0]); a1p[1][1] = fma2(dz1, ks1, a1p[1][1]);
        a1p[2][0] = fma2(dz2, ks0, a1p[2][0]); a1p[2][1] = fma2(dz2, ks1, a1p[2][1]);
        a1p[3][0] = fma2(dz3, ks0, a1p[3][0]); a1p[3][1] = fma2(dz3, ks1, a1p[3][1]);
        float4 dq = *(const float4*)&sdy[t*64 + e0];
        ulonglong2 hq = *(const ulonglong2*)&sh[t*128 + h0];
        u64 hs0 = mul2(hq.x, cdp), hs1 = mul2(hq.y, cdp);
        u64 dy0 = splat2(dq.x), dy1 = splat2(dq.y);
        u64 dy2 = splat2(dq.z), dy3 = splat2(dq.w);
        a2p[0][0] = fma2(dy0, hs0, a2p[0][0]); a2p[0][1] = fma2(dy0, hs1, a2p[0][1]);
        a2p[1][0] = fma2(dy1, hs0, a2p[1][0]); a2p[1][1] = fma2(dy1, hs1, a2p[1][1]);
        a2p[2][0] = fma2(dy2, hs0, a2p[2][0]); a2p[2][1] = fma2(dy2, hs1, a2p[2][1]);
        a2p[3][0] = fma2(dy3, hs0, a2p[3][0]); a2p[3][1] = fma2(dy3, hs1, a2p[3][1]);
    }

    float* p = g_part + (size_t)bid * PARTSZ2;
    #pragma unroll
    for (int i = 0; i < 4; i++) {
        float2 lo = up2(a1p[i][0]), hi = up2(a1p[i][1]);
        *(float4*)&p[OF2_W1D + (h0 + i)*64 + e0] = make_float4(lo.x, lo.y, hi.x, hi.y);
    }
    #pragma unroll
    for (int j = 0; j < 4; j++) {
        float2 lo = up2(a2p[j][0]), hi = up2(a2p[j][1]);
        *(float4*)&p[OF2_W2D + (e0 + j)*128 + h0] = make_float4(lo.x, lo.y, hi.x, hi.y);
    }
    if (tid < 128) {
        float aD = 0.f;
        for (int t = 0; t < TC; t++) aD += scD[t] * sdz[t*128 + tid];
        p[OF2_B1D + tid] = aD;
    } else if (tid < 192) {
        int e = tid - 128;
        float aD = 0.f;
        for (int t = 0; t < TC; t++) aD += scD[t] * sdy[t*64 + e];
        p[OF2_B2D + e] = aD;
    }
    if (tid < TC) g_lossp[b*Tz + t0 + tid] = sloss[tid];

    // ---- correction (last chunk per batch; scalar, small) ----
    if ((bid & 15) == 15) {
        float c1[4][4], c2[4][4];
        #pragma unroll
        for (int i = 0; i < 4; i++)
            #pragma unroll
            for (int j = 0; j < 4; j++) { c1[i][j] = 0.f; c2[j][i] = 0.f; }
        for (int t = 16; t < TC; t++) {
            float cc = scC[t];
            float4 kq = *(const float4*)&sk[t*64 + e0];
            float ks[4] = {cc*kq.x, cc*kq.y, cc*kq.z, cc*kq.w};
            float4 zq = *(const float4*)&sdz[t*128 + h0];
            float dzv[4] = {zq.x, zq.y, zq.z, zq.w};
            #pragma unroll
            for (int i = 0; i < 4; i++)
                #pragma unroll
                for (int j = 0; j < 4; j++) c1[i][j] += dzv[i] * ks[j];
            float4 dq = *(const float4*)&sdy[t*64 + e0];
            float dys[4] = {cc*dq.x, cc*dq.y, cc*dq.z, cc*dq.w};
            float4 hq = *(const float4*)&sh[t*128 + h0];
            float hv[4] = {hq.x, hq.y, hq.z, hq.w};
            #pragma unroll
            for (int j = 0; j < 4; j++)
                #pragma unroll
                for (int i = 0; i < 4; i++) c2[j][i] += dys[j] * hv[i];
        }
        float* q = g_corr + (size_t)b * PARTSZ2;
        #pragma unroll
        for (int i = 0; i < 4; i++)
            *(float4*)&q[OF2_W1D + (h0 + i)*64 + e0] =
                make_float4(c1[i][0], c1[i][1], c1[i][2], c1[i][3]);
        #pragma unroll
        for (int j = 0; j < 4; j++)
            *(float4*)&q[OF2_W2D + (e0 + j)*128 + h0] =
                make_float4(c2[j][0], c2[j][1], c2[j][2], c2[j][3]);
        if (tid < 128) {
            float aC = 0.f;
            for (int t = 16; t < TC; t++) aC += scC[t] * sdz[t*128 + tid];
            q[OF2_B1D + tid] = aC;
        } else if (tid < 192) {
            int e = tid - 128;
            float aC = 0.f;
            for (int t = 16; t < TC; t++) aC += scC[t] * sdy[t*64 + e];
            q[OF2_B2D + e] = aC;
        }
    }

    // ---- grid barrier #2, then fused output reduction ----
    grid_barrier(tid);

    const float qT = __expf(-26.262166726f);    // 0.95^512
    const float aT = qT * 1.0010537407f;        // qT/(1-beta/eta)
    int gt = bid * 512 + tid;
    if (gt < 512) {
        float s = 0.f;
        #pragma unroll
        for (int bb = 0; bb < Bz; bb++) s += g_lossp[bb*Tz + gt];
        out[O_LOSS + gt] = s * (1.f/512.f);
        return;
    }
    int j = gt - 512;
    int ofD, nvec_b, segM, segS;
    const float* S0p;
    if (j < 16384) {
        ofD = OF2_W1D; nvec_b = 2048; segM = O_MW1; segS = O_SW1; S0p = SW1;
    } else if ((j -= 16384) < 256) {
        ofD = OF2_B1D; nvec_b = 32;   segM = O_MB1; segS = O_SB1; S0p = Sb1;
    } else if ((j -= 256) < 16384) {
        ofD = OF2_W2D; nvec_b = 2048; segM = O_MW2; segS = O_SW2; S0p = SW2;
    } else if ((j -= 16384) < 128) {
        ofD = OF2_B2D; nvec_b = 16;   segM = O_MB2; segS = O_SB2; S0p = Sb2;
    } else return;

    int bb = j / nvec_b;
    int r = (j - bb*nvec_b) * 4;
    const float* pp = g_part + (size_t)(bb*NC) * PARTSZ2 + ofD + r;
    float4 rD = make_float4(0.f, 0.f, 0.f, 0.f);
    #pragma unroll
    for (int c = 0; c < NC; c++) {
        float4 v = *(const float4*)(pp + (size_t)c * PARTSZ2);
        rD.x += v.x; rD.y += v.y; rD.z += v.z; rD.w += v.w;
    }
    float4 cr = *(const float4*)(g_corr + (size_t)bb * PARTSZ2 + ofD + r);
    int gidx = bb * (nvec_b*4) + r;
    float4 s0 = *(const float4*)(S0p + gidx);
    float4 M, S;
    M.x = aT*s0.x + rD.x*INV949 + cr.x;  S.x = qT*s0.x + rD.x;
    M.y = aT*s0.y + rD.y*INV949 + cr.y;  S.y = qT*s0.y + rD.y;
    M.z = aT*s0.z + rD.z*INV949 + cr.z;  S.z = qT*s0.z + rD.z;
    M.w = aT*s0.w + rD.w*INV949 + cr.w;  S.w = qT*s0.w + rD.w;
    *(float4*)(out + segM + gidx) = M;
    *(float4*)(out + segS + gidx) = S;
}

extern "C" void kernel_launch(void* const* d_in, const int* in_sizes, int n_in,
                              void* d_out, int out_size) {
    const float* x   = (const float*)d_in[0];
    const float* WK  = (const float*)d_in[1];
    const float* WV  = (const float*)d_in[2];
    const float* W1  = (const float*)d_in[3];
    const float* b1  = (const float*)d_in[4];
    const float* W2  = (const float*)d_in[5];
    const float* b2  = (const float*)d_in[6];
    const float* SW1 = (const float*)d_in[7];
    const float* Sb1 = (const float*)d_in[8];
    const float* SW2 = (const float*)d_in[9];
    const float* Sb2 = (const float*)d_in[10];
    float* out = (float*)d_out;

    static const size_t smem_main = SM_FLOATS * sizeof(float);
    cudaFuncSetAttribute(k_main, cudaFuncAttributeMaxDynamicSharedMemorySize,
                         (int)smem_main);

    k_main<<<NCTA, 512, smem_main>>>(x, WK, WV, W1, b1, W2, b2,
                                     SW1, Sb1, SW2, Sb2, out);
}